// round 5
// baseline (speedup 1.0000x reference)
#include <cuda_runtime.h>
#include <cuda_bf16.h>

#define NN 100000
#define EE 1250000
#define HH 64
#define GG 128
#define CC 10
#define NB 98           // ceil(NN/1024) scan blocks

// Scratch (device globals; only dereferenced from device code)
__device__ int   g_is64;             // 1 if edge_index/batch arrive as int64
__device__ int   g_degi[NN];
__device__ float g_dinv[NN];
__device__ int   g_rowptr[NN + 1];
__device__ int   g_cursor[NN];
__device__ int   g_blksum[NB];
__device__ int   g_csr_src[EE];
__device__ float g_csr_nrm[EE];
__device__ float g_bufA[NN * HH];   // h @ W (gather source)
__device__ float g_bufB[NN * HH];   // layer output / next input

// index load that works for both int32 and int64 payloads
__device__ __forceinline__ int load_idx(const void* p, long long i, int is64) {
    if (is64) return (int)((const long long*)p)[i];
    return ((const int*)p)[i];
}

// ---------------------------------------------------------------------------
// dtype detector: int64 data viewed as int32 has zeros at all odd positions
// (high words of values < 2^31). Genuine int32 node ids are ~never 0 there.
// ---------------------------------------------------------------------------
__global__ void k_detect(const void* ei_raw) {
    __shared__ int cnt;
    if (threadIdx.x == 0) cnt = 0;
    __syncthreads();
    const int* p = (const int*)ei_raw;
    int z = 0;
    for (int i = threadIdx.x; i < 4096; i += 256)
        if (p[2 * i + 1] == 0) z++;
    atomicAdd(&cnt, z);
    __syncthreads();
    if (threadIdx.x == 0) g_is64 = (cnt > 2048) ? 1 : 0;
}

// ---------------------------------------------------------------------------
// CSR build: histogram -> scan -> scatter
// ---------------------------------------------------------------------------
__global__ void k_zero_deg() {
    int i = blockIdx.x * blockDim.x + threadIdx.x;
    if (i < NN) g_degi[i] = 0;
}

__global__ void k_hist(const void* __restrict__ ei) {
    int e = blockIdx.x * blockDim.x + threadIdx.x;
    if (e < EE) {
        int d = load_idx(ei, (long long)EE + e, g_is64);
        atomicAdd(&g_degi[d], 1);
    }
}

__global__ void k_dinv() {
    int i = blockIdx.x * blockDim.x + threadIdx.x;
    if (i < NN) g_dinv[i] = rsqrtf(1.0f + (float)g_degi[i]);  // +1 self-loop
}

// block-level exclusive scan of g_degi -> g_rowptr, block totals -> g_blksum
__global__ void k_scan1() {
    __shared__ int sh[1024];
    int t = threadIdx.x;
    int i = blockIdx.x * 1024 + t;
    int v = (i < NN) ? g_degi[i] : 0;
    sh[t] = v;
    __syncthreads();
    #pragma unroll
    for (int off = 1; off < 1024; off <<= 1) {
        int add = (t >= off) ? sh[t - off] : 0;
        __syncthreads();
        sh[t] += add;
        __syncthreads();
    }
    if (i < NN) g_rowptr[i] = sh[t] - v;          // exclusive
    if (t == 1023) g_blksum[blockIdx.x] = sh[t];
}

__global__ void k_scan2() {   // single thread: scan NB block sums
    if (threadIdx.x == 0) {
        int acc = 0;
        for (int b = 0; b < NB; b++) {
            int v = g_blksum[b];
            g_blksum[b] = acc;
            acc += v;
        }
        g_rowptr[NN] = acc;   // == EE
    }
}

__global__ void k_scan3() {
    int i = blockIdx.x * blockDim.x + threadIdx.x;
    if (i < NN) {
        int v = g_rowptr[i] + g_blksum[i >> 10];
        g_rowptr[i] = v;
        g_cursor[i] = v;
    }
}

__global__ void k_scatter(const void* __restrict__ ei) {
    int e = blockIdx.x * blockDim.x + threadIdx.x;
    if (e >= EE) return;
    int is64 = g_is64;
    int s = load_idx(ei, e, is64);
    int d = load_idx(ei, (long long)EE + e, is64);
    int pos = atomicAdd(&g_cursor[d], 1);
    g_csr_src[pos] = s;
    g_csr_nrm[pos] = g_dinv[s] * g_dinv[d];
}

// ---------------------------------------------------------------------------
// GEMM: g_bufA = act(h) @ W. Layer 1 reads x_in; layers 2/3 read g_bufB.
// 256 threads/block, 64 rows/block, 4x4 register tile.
// ---------------------------------------------------------------------------
__global__ void k_gemm(const float* __restrict__ x_in, const float* __restrict__ W,
                       int use_bufB, int relu) {
    __shared__ float Ws[64 * 64];
    __shared__ float hs[64 * 65];
    int t = threadIdx.x;
    int base = blockIdx.x * 64;
    const float* __restrict__ h = use_bufB ? (const float*)g_bufB : x_in;

    #pragma unroll
    for (int i = t; i < 4096; i += 256) Ws[i] = W[i];
    #pragma unroll
    for (int i = t; i < 4096; i += 256) {
        int r = i >> 6, c = i & 63;
        int row = base + r;
        float v = (row < NN) ? h[(size_t)row * 64 + c] : 0.0f;
        if (relu) v = fmaxf(v, 0.0f);
        hs[r * 65 + c] = v;
    }
    __syncthreads();

    int tx = t & 15, ty = t >> 4;
    float acc[4][4] = {};
    #pragma unroll
    for (int k = 0; k < 64; k++) {
        float w0 = Ws[k * 64 + tx];
        float w1 = Ws[k * 64 + tx + 16];
        float w2 = Ws[k * 64 + tx + 32];
        float w3 = Ws[k * 64 + tx + 48];
        #pragma unroll
        for (int i = 0; i < 4; i++) {
            float a = hs[(ty * 4 + i) * 65 + k];
            acc[i][0] = fmaf(a, w0, acc[i][0]);
            acc[i][1] = fmaf(a, w1, acc[i][1]);
            acc[i][2] = fmaf(a, w2, acc[i][2]);
            acc[i][3] = fmaf(a, w3, acc[i][3]);
        }
    }
    #pragma unroll
    for (int i = 0; i < 4; i++) {
        int row = base + ty * 4 + i;
        if (row < NN) {
            #pragma unroll
            for (int j = 0; j < 4; j++)
                g_bufA[(size_t)row * 64 + tx + 16 * j] = acc[i][j];
        }
    }
}

// ---------------------------------------------------------------------------
// Aggregation (atomic-free): one warp per dst node.
//   bufB[n] = b + dinv[n]^2 * bufA[n] + sum_{e in CSR[n]} nrm_e * bufA[src_e]
// ---------------------------------------------------------------------------
__global__ void k_agg(const float* __restrict__ b) {
    int warp = (blockIdx.x * blockDim.x + threadIdx.x) >> 5;
    if (warp >= NN) return;
    int lane = threadIdx.x & 31;
    int n = warp;

    int beg = g_rowptr[n];
    int end = g_rowptr[n + 1];
    float di = g_dinv[n];
    float s2 = di * di;

    float2 v0 = *(const float2*)(g_bufA + (size_t)n * 64 + 2 * lane);
    float2 bb = *(const float2*)(b + 2 * lane);
    float2 acc;
    acc.x = fmaf(s2, v0.x, bb.x);
    acc.y = fmaf(s2, v0.y, bb.y);

    for (int base = beg; base < end; base += 32) {
        int e = base + lane;
        int src = 0; float nrm = 0.0f;
        if (e < end) { src = g_csr_src[e]; nrm = g_csr_nrm[e]; }
        int cnt = min(32, end - base);
        for (int j = 0; j < cnt; j++) {
            int   sj = __shfl_sync(0xffffffffu, src, j);
            float nj = __shfl_sync(0xffffffffu, nrm, j);
            float2 v = *(const float2*)(g_bufA + (size_t)sj * 64 + 2 * lane);
            acc.x = fmaf(nj, v.x, acc.x);
            acc.y = fmaf(nj, v.y, acc.y);
        }
    }
    *(float2*)(g_bufB + (size_t)n * 64 + 2 * lane) = acc;
}

// ---------------------------------------------------------------------------
// Fused mean-pool + head. batch is sorted -> binary search per graph.
// One block per graph (128 blocks), 256 threads = 16 node-groups x 16 quads.
// ---------------------------------------------------------------------------
__global__ void k_pool_head(const void* __restrict__ batch,
                            const float* __restrict__ Wl,
                            const float* __restrict__ bl,
                            float* __restrict__ out) {
    __shared__ float4 sh[16][16];
    __shared__ float pooled[64];
    int g = blockIdx.x;
    int t = threadIdx.x;
    int q = t & 15;          // feature quad (4 floats)
    int grp = t >> 4;        // node group
    int is64 = g_is64;

    int lo = 0, hi = NN;
    while (lo < hi) { int m = (lo + hi) >> 1; if (load_idx(batch, m, is64) < g) lo = m + 1; else hi = m; }
    int start = lo;
    lo = start; hi = NN;
    while (lo < hi) { int m = (lo + hi) >> 1; if (load_idx(batch, m, is64) < g + 1) lo = m + 1; else hi = m; }
    int end = lo;
    float inv = 1.0f / fmaxf((float)(end - start), 1.0f);

    float4 acc = make_float4(0.f, 0.f, 0.f, 0.f);
    for (int i = start + grp; i < end; i += 16) {
        float4 v = *(const float4*)(g_bufB + (size_t)i * 64 + 4 * q);
        acc.x += v.x; acc.y += v.y; acc.z += v.z; acc.w += v.w;
    }
    sh[grp][q] = acc;
    __syncthreads();

    if (t < 16) {
        float4 s = make_float4(0.f, 0.f, 0.f, 0.f);
        #pragma unroll
        for (int j = 0; j < 16; j++) {
            float4 v = sh[j][t];
            s.x += v.x; s.y += v.y; s.z += v.z; s.w += v.w;
        }
        pooled[4 * t + 0] = s.x * inv;
        pooled[4 * t + 1] = s.y * inv;
        pooled[4 * t + 2] = s.z * inv;
        pooled[4 * t + 3] = s.w * inv;
    }
    __syncthreads();

    if (t < CC) {
        float acc2 = bl[t];
        #pragma unroll
        for (int f = 0; f < HH; f++)
            acc2 = fmaf(pooled[f], Wl[f * CC + t], acc2);
        out[g * CC + t] = acc2;
    }
}

// ---------------------------------------------------------------------------
extern "C" void kernel_launch(void* const* d_in, const int* in_sizes, int n_in,
                              void* d_out, int out_size) {
    const float* x     = (const float*)d_in[0];
    const void*  ei    = d_in[1];
    const void*  batch = d_in[2];
    const float* W1    = (const float*)d_in[3];
    const float* b1    = (const float*)d_in[4];
    const float* W2    = (const float*)d_in[5];
    const float* b2    = (const float*)d_in[6];
    const float* W3    = (const float*)d_in[7];
    const float* b3    = (const float*)d_in[8];
    const float* Wl    = (const float*)d_in[9];
    const float* bl    = (const float*)d_in[10];
    float* out = (float*)d_out;

    const int T = 256;
    const int gN   = (NN + T - 1) / T;
    const int gE   = (EE + T - 1) / T;
    const int gRow = (NN + 63) / 64;
    const int gAgg = (NN * 32 + T - 1) / T;

    // dtype detection + CSR build
    k_detect<<<1, T>>>(ei);
    k_zero_deg<<<gN, T>>>();
    k_hist<<<gE, T>>>(ei);
    k_dinv<<<gN, T>>>();
    k_scan1<<<NB, 1024>>>();
    k_scan2<<<1, 32>>>();
    k_scan3<<<gN, T>>>();
    k_scatter<<<gE, T>>>(ei);

    // layer 1
    k_gemm<<<gRow, T>>>(x, W1, 0, 0);
    k_agg<<<gAgg, T>>>(b1);
    // layer 2
    k_gemm<<<gRow, T>>>(x, W2, 1, 1);
    k_agg<<<gAgg, T>>>(b2);
    // layer 3
    k_gemm<<<gRow, T>>>(x, W3, 1, 1);
    k_agg<<<gAgg, T>>>(b3);

    // pooling + head
    k_pool_head<<<GG, T>>>(batch, Wl, bl, out);
}